// round 1
// baseline (speedup 1.0000x reference)
#include <cuda_runtime.h>
#include <cuda_bf16.h>
#include <math.h>

// ---------------- problem constants ----------------
#define DIMC 768
#define HEADS 12
#define HEAD_DIM 64
#define GRID_HW 14
#define NTOK 196            // 14*14
#define BATCH 256
#define VIEWS 8
#define BS 32               // BATCH / VIEWS
#define GROUPS 49           // 7*7
#define SEQ 32              // t1*t2*views = 2*2*8
#define M_TOT 50176         // BATCH*NTOK
#define TOTAL_ELEMS 38535168 // 256*196*768
#define SCALE_ATTN 0.125f   // 64^-0.5

// ---------------- scratch (static device memory; no allocs allowed) ----------------
__device__ float g_q[TOTAL_ELEMS];
__device__ float g_k[TOTAL_ELEMS];
__device__ float g_v[TOTAL_ELEMS];
__device__ float g_o[TOTAL_ELEMS];

// ---------------- SGEMM: C[M x N] = A[M x K] * B[K x N] (+bias) ----------------
// Block tile 128x128, K tile 8, 256 threads, 8x8 per-thread micro tile.
// All dims divide exactly for this problem (M=50176, N=768, K=768).
#define BM 128
#define BN 128
#define BKK 8
#define TM 8
#define TN 8

__device__ __forceinline__ void sgemm_body(const float* __restrict__ A,
                                           const float* __restrict__ B,
                                           float* __restrict__ C,
                                           const float* __restrict__ bias,
                                           int M, int N, int K)
{
    __shared__ float As[BKK][BM];
    __shared__ float Bs[BKK][BN];

    const int tid = threadIdx.x;            // 0..255
    const int tx = tid & 15;                // 0..15
    const int ty = tid >> 4;                // 0..15
    const int row0 = blockIdx.y * BM;
    const int col0 = blockIdx.x * BN;

    float acc[TM][TN];
#pragma unroll
    for (int i = 0; i < TM; i++)
#pragma unroll
        for (int j = 0; j < TN; j++) acc[i][j] = 0.f;

    // A-load mapping: r = tid>>1 (0..127), quad = tid&1 (two float4 per row of 8)
    const int ar = tid >> 1;
    const int aq = (tid & 1) << 2;
    // B-load mapping: r = tid>>5 (0..7), c4 = (tid&31)*4
    const int br = tid >> 5;
    const int bc = (tid & 31) << 2;

    for (int k0 = 0; k0 < K; k0 += BKK) {
        float4 av = *(const float4*)(A + (size_t)(row0 + ar) * K + k0 + aq);
        As[aq + 0][ar] = av.x;
        As[aq + 1][ar] = av.y;
        As[aq + 2][ar] = av.z;
        As[aq + 3][ar] = av.w;

        float4 bv = *(const float4*)(B + (size_t)(k0 + br) * N + col0 + bc);
        *(float4*)&Bs[br][bc] = bv;

        __syncthreads();

#pragma unroll
        for (int kk = 0; kk < BKK; kk++) {
            float a[TM], b[TN];
            *(float4*)&a[0] = *(const float4*)&As[kk][ty * TM + 0];
            *(float4*)&a[4] = *(const float4*)&As[kk][ty * TM + 4];
            *(float4*)&b[0] = *(const float4*)&Bs[kk][tx * TN + 0];
            *(float4*)&b[4] = *(const float4*)&Bs[kk][tx * TN + 4];
#pragma unroll
            for (int i = 0; i < TM; i++)
#pragma unroll
                for (int j = 0; j < TN; j++)
                    acc[i][j] = fmaf(a[i], b[j], acc[i][j]);
        }
        __syncthreads();
    }

    // epilogue
#pragma unroll
    for (int i = 0; i < TM; i++) {
        const size_t crow = (size_t)(row0 + ty * TM + i) * N + col0 + tx * TN;
#pragma unroll
        for (int j = 0; j < TN; j += 4) {
            float4 val;
            val.x = acc[i][j + 0];
            val.y = acc[i][j + 1];
            val.z = acc[i][j + 2];
            val.w = acc[i][j + 3];
            if (bias) {
                const int cb = col0 + tx * TN + j;
                val.x += bias[cb + 0];
                val.y += bias[cb + 1];
                val.z += bias[cb + 2];
                val.w += bias[cb + 3];
            }
            *(float4*)(C + crow + j) = val;
        }
    }
}

__global__ void __launch_bounds__(256)
sgemm_qkv_kernel(const float* __restrict__ X,
                 const float* __restrict__ Wq,
                 const float* __restrict__ Wk,
                 const float* __restrict__ Wv)
{
    const float* W;
    float* C;
    if (blockIdx.z == 0)      { W = Wq; C = g_q; }
    else if (blockIdx.z == 1) { W = Wk; C = g_k; }
    else                      { W = Wv; C = g_v; }
    sgemm_body(X, W, C, nullptr, M_TOT, DIMC, DIMC);
}

__global__ void __launch_bounds__(256)
sgemm_proj_kernel(const float* __restrict__ Wp,
                  const float* __restrict__ bp,
                  float* __restrict__ out)
{
    sgemm_body(g_o, Wp, out, bp, M_TOT, DIMC, DIMC);
}

// ---------------- grouped attention ----------------
// One block per (b_idx, s, h): SEQ=32 tokens, HEAD_DIM=64.
// smem padded (65 / 33) for conflict-free column access.
__global__ void __launch_bounds__(128)
attn_kernel(float* __restrict__ O)
{
    const int bx = blockIdx.x;
    const int h  = bx % HEADS;
    const int s  = (bx / HEADS) % GROUPS;
    const int bi = bx / (HEADS * GROUPS);
    const int s1 = s / 7, s2 = s % 7;

    __shared__ float qs[SEQ * 65];
    __shared__ float ks[SEQ * 65];
    __shared__ float vs[SEQ * 65];
    __shared__ float Sm[SEQ * 33];

    const int tid = threadIdx.x; // 128

    // gather q,k,v tiles (each row of 64 fp32 is a contiguous 256B global segment)
    for (int idx = tid; idx < SEQ * HEAD_DIM; idx += 128) {
        const int j = idx >> 6, d = idx & 63;
        const int vv = j & 7, t2 = (j >> 3) & 1, t1 = j >> 4;
        const int B = bi * VIEWS + vv;
        const int n = t1 * 98 + s1 * 14 + t2 * 7 + s2;
        const size_t g = ((size_t)(B * NTOK + n)) * DIMC + h * HEAD_DIM + d;
        qs[j * 65 + d] = g_q[g];
        ks[j * 65 + d] = g_k[g];
        vs[j * 65 + d] = g_v[g];
    }
    __syncthreads();

    // scores: warp w handles rows 8w..8w+7, lane = key index (conflict-free via pad 65)
    const int w = tid >> 5, lane = tid & 31;
#pragma unroll 1
    for (int r = 0; r < 8; r++) {
        const int i = w * 8 + r;
        float sum = 0.f;
#pragma unroll
        for (int d = 0; d < HEAD_DIM; d++)
            sum = fmaf(qs[i * 65 + d], ks[lane * 65 + d], sum);
        Sm[i * 33 + lane] = sum * SCALE_ATTN;
    }
    __syncthreads();

    // softmax, one thread per row
    if (tid < SEQ) {
        float m = -1e30f;
#pragma unroll
        for (int j = 0; j < SEQ; j++) m = fmaxf(m, Sm[tid * 33 + j]);
        float sum = 0.f;
#pragma unroll
        for (int j = 0; j < SEQ; j++) {
            const float e = __expf(Sm[tid * 33 + j] - m);
            Sm[tid * 33 + j] = e;
            sum += e;
        }
        const float inv = 1.f / sum;
#pragma unroll
        for (int j = 0; j < SEQ; j++) Sm[tid * 33 + j] *= inv;
    }
    __syncthreads();

    // O = P @ V, scatter back to (B, n, h*64+d) layout
    for (int idx = tid; idx < SEQ * HEAD_DIM; idx += 128) {
        const int i = idx >> 6, d = idx & 63;
        float o = 0.f;
#pragma unroll
        for (int j = 0; j < SEQ; j++)
            o = fmaf(Sm[i * 33 + j], vs[j * 65 + d], o);
        const int vv = i & 7, t2 = (i >> 3) & 1, t1 = i >> 4;
        const int B = bi * VIEWS + vv;
        const int n = t1 * 98 + s1 * 14 + t2 * 7 + s2;
        O[((size_t)(B * NTOK + n)) * DIMC + h * HEAD_DIM + d] = o;
    }
}

// ---------------- depthwise 3x3 conv on V, accumulate into O ----------------
__global__ void __launch_bounds__(256)
conv_kernel(const float* __restrict__ cw,
            const float* __restrict__ cb,
            float* __restrict__ O)
{
    const size_t gid = (size_t)blockIdx.x * 256 + threadIdx.x;
    if (gid >= (size_t)TOTAL_ELEMS) return;
    const int c  = (int)(gid % DIMC);
    const int sp = (int)((gid / DIMC) % NTOK);
    const int B  = (int)(gid / ((size_t)DIMC * NTOK));
    const int x  = sp % GRID_HW, y = sp / GRID_HW;

    float acc = cb[c];
#pragma unroll
    for (int dy = 0; dy < 3; dy++) {
        const int yy = y + dy - 1;
        if (yy < 0 || yy >= GRID_HW) continue;
#pragma unroll
        for (int dx = 0; dx < 3; dx++) {
            const int xx = x + dx - 1;
            if (xx < 0 || xx >= GRID_HW) continue;
            acc = fmaf(g_v[((size_t)(B * NTOK) + yy * GRID_HW + xx) * DIMC + c],
                       cw[c * 9 + dy * 3 + dx], acc);
        }
    }
    O[gid] += acc;
}

// ---------------- launch ----------------
extern "C" void kernel_launch(void* const* d_in, const int* in_sizes, int n_in,
                              void* d_out, int out_size)
{
    const float* x = (const float*)d_in[0];
    // view_num may or may not appear as a 1-element input; detect by size.
    int base = (n_in > 1 && in_sizes[1] == 1) ? 2 : 1;
    const float* Wq = (const float*)d_in[base + 0];
    const float* Wk = (const float*)d_in[base + 1];
    const float* Wv = (const float*)d_in[base + 2];
    const float* Wp = (const float*)d_in[base + 3];
    const float* bp = (const float*)d_in[base + 4];
    const float* cw = (const float*)d_in[base + 5];
    const float* cb = (const float*)d_in[base + 6];
    float* out = (float*)d_out;

    float* o_ptr;
    cudaGetSymbolAddress((void**)&o_ptr, g_o);

    dim3 gq(DIMC / BN, M_TOT / BM, 3);
    sgemm_qkv_kernel<<<gq, 256>>>(x, Wq, Wk, Wv);

    attn_kernel<<<BS * GROUPS * HEADS, 128>>>(o_ptr);

    conv_kernel<<<(TOTAL_ELEMS + 255) / 256, 256>>>(cw, cb, o_ptr);

    dim3 gp(DIMC / BN, M_TOT / BM);
    sgemm_proj_kernel<<<gp, 256>>>(Wp, bp, out);
}

// round 2
// speedup vs baseline: 2.4472x; 2.4472x over previous
#include <cuda_runtime.h>
#include <cuda_bf16.h>
#include <math.h>

// ---------------- problem constants ----------------
#define DIMC 768
#define HEADS 12
#define HEAD_DIM 64
#define GRID_HW 14
#define NTOK 196
#define BATCH 256
#define VIEWS 8
#define BS 32
#define GROUPS 49
#define SEQ 32
#define M_TOT 50176
#define TOTAL_ELEMS 38535168
#define SCALE_ATTN 0.125f

// ---------------- scratch ----------------
__device__ float g_q[TOTAL_ELEMS];
__device__ float g_k[TOTAL_ELEMS];
__device__ float g_v[TOTAL_ELEMS];
__device__ float g_o[TOTAL_ELEMS];

// ---------------- TF32 tensor-core GEMM ----------------
// C[M=50176 x N=768] = A[M x K=768] * B[K x N] (+bias), all row-major fp32.
// Block 128x128, BK=16, 256 threads = 8 warps, warp tile 64x32 (4x4 m16n8k8).

__device__ __forceinline__ unsigned f2tf(float f) {
    unsigned r;
    asm("cvt.rna.tf32.f32 %0, %1;" : "=r"(r) : "f"(f));
    return r;
}

__device__ __forceinline__ void mma_tf32(float c[4], const unsigned a[4], const unsigned b[2]) {
    asm volatile(
        "mma.sync.aligned.m16n8k8.row.col.f32.tf32.tf32.f32 "
        "{%0,%1,%2,%3}, {%4,%5,%6,%7}, {%8,%9}, {%0,%1,%2,%3};"
        : "+f"(c[0]), "+f"(c[1]), "+f"(c[2]), "+f"(c[3])
        : "r"(a[0]), "r"(a[1]), "r"(a[2]), "r"(a[3]), "r"(b[0]), "r"(b[1]));
}

#define AS_STRIDE 20   // 16 + 4 pad: conflict-free a-frag LDS
#define BS_STRIDE 136  // 128 + 8 pad: conflict-free b-frag LDS

__device__ __forceinline__ void tgemm_body(const float* __restrict__ A,
                                           const float* __restrict__ B,
                                           float* __restrict__ C,
                                           const float* __restrict__ bias)
{
    __shared__ unsigned As[128 * AS_STRIDE];
    __shared__ unsigned Bs[16 * BS_STRIDE];

    const int tid  = threadIdx.x;
    const int wid  = tid >> 5, lane = tid & 31;
    const int g    = lane >> 2, t = lane & 3;
    const int wm   = (wid & 1) * 64;
    const int wn   = (wid >> 1) * 32;
    const int row0 = blockIdx.y * 128;
    const int col0 = blockIdx.x * 128;

    // global-load mappings
    const int arow = tid >> 2;            // 0..63 (and +64)
    const int aq   = (tid & 3) << 2;      // 0,4,8,12
    const int brow = tid >> 5;            // 0..7 (and +8)
    const int bc   = (tid & 31) << 2;     // 0..124

    const float* Ap0 = A + (size_t)(row0 + arow) * DIMC + aq;
    const float* Ap1 = A + (size_t)(row0 + arow + 64) * DIMC + aq;
    const float* Bp0 = B + (size_t)brow * DIMC + col0 + bc;
    const float* Bp1 = B + (size_t)(brow + 8) * DIMC + col0 + bc;

    float acc[4][4][4];
#pragma unroll
    for (int i = 0; i < 4; i++)
#pragma unroll
        for (int j = 0; j < 4; j++)
#pragma unroll
            for (int k = 0; k < 4; k++) acc[i][j][k] = 0.f;

    float4 pa0, pa1, pb0, pb1;

    // preload tile 0
    pa0 = *(const float4*)(Ap0);
    pa1 = *(const float4*)(Ap1);
    pb0 = *(const float4*)(Bp0);
    pb1 = *(const float4*)(Bp1);

    // store tile 0
    {
        uint4 u0 = make_uint4(f2tf(pa0.x), f2tf(pa0.y), f2tf(pa0.z), f2tf(pa0.w));
        uint4 u1 = make_uint4(f2tf(pa1.x), f2tf(pa1.y), f2tf(pa1.z), f2tf(pa1.w));
        *(uint4*)&As[arow * AS_STRIDE + aq]        = u0;
        *(uint4*)&As[(arow + 64) * AS_STRIDE + aq] = u1;
        uint4 v0 = make_uint4(f2tf(pb0.x), f2tf(pb0.y), f2tf(pb0.z), f2tf(pb0.w));
        uint4 v1 = make_uint4(f2tf(pb1.x), f2tf(pb1.y), f2tf(pb1.z), f2tf(pb1.w));
        *(uint4*)&Bs[brow * BS_STRIDE + bc]       = v0;
        *(uint4*)&Bs[(brow + 8) * BS_STRIDE + bc] = v1;
    }
    __syncthreads();

    for (int k0 = 0; k0 < DIMC; k0 += 16) {
        const bool notlast = (k0 + 16 < DIMC);
        if (notlast) {
            pa0 = *(const float4*)(Ap0 + k0 + 16);
            pa1 = *(const float4*)(Ap1 + k0 + 16);
            pb0 = *(const float4*)(Bp0 + (size_t)(k0 + 16) * DIMC);
            pb1 = *(const float4*)(Bp1 + (size_t)(k0 + 16) * DIMC);
        }

#pragma unroll
        for (int kk = 0; kk < 16; kk += 8) {
            unsigned af[4][4], bf[4][2];
#pragma unroll
            for (int mt = 0; mt < 4; mt++) {
                const int m = wm + mt * 16 + g;
                af[mt][0] = As[m * AS_STRIDE + kk + t];
                af[mt][1] = As[(m + 8) * AS_STRIDE + kk + t];
                af[mt][2] = As[m * AS_STRIDE + kk + t + 4];
                af[mt][3] = As[(m + 8) * AS_STRIDE + kk + t + 4];
            }
#pragma unroll
            for (int nt = 0; nt < 4; nt++) {
                const int n = wn + nt * 8 + g;
                bf[nt][0] = Bs[(kk + t) * BS_STRIDE + n];
                bf[nt][1] = Bs[(kk + t + 4) * BS_STRIDE + n];
            }
#pragma unroll
            for (int mt = 0; mt < 4; mt++)
#pragma unroll
                for (int nt = 0; nt < 4; nt++)
                    mma_tf32(acc[mt][nt], af[mt], bf[nt]);
        }

        if (notlast) {
            __syncthreads();
            uint4 u0 = make_uint4(f2tf(pa0.x), f2tf(pa0.y), f2tf(pa0.z), f2tf(pa0.w));
            uint4 u1 = make_uint4(f2tf(pa1.x), f2tf(pa1.y), f2tf(pa1.z), f2tf(pa1.w));
            *(uint4*)&As[arow * AS_STRIDE + aq]        = u0;
            *(uint4*)&As[(arow + 64) * AS_STRIDE + aq] = u1;
            uint4 v0 = make_uint4(f2tf(pb0.x), f2tf(pb0.y), f2tf(pb0.z), f2tf(pb0.w));
            uint4 v1 = make_uint4(f2tf(pb1.x), f2tf(pb1.y), f2tf(pb1.z), f2tf(pb1.w));
            *(uint4*)&Bs[brow * BS_STRIDE + bc]       = v0;
            *(uint4*)&Bs[(brow + 8) * BS_STRIDE + bc] = v1;
            __syncthreads();
        }
    }

    // epilogue: c0/c1 at (row, 2t), (row, 2t+1); c2/c3 at row+8
#pragma unroll
    for (int mt = 0; mt < 4; mt++) {
        const int r = row0 + wm + mt * 16 + g;
#pragma unroll
        for (int nt = 0; nt < 4; nt++) {
            const int c = col0 + wn + nt * 8 + 2 * t;
            float b0 = 0.f, b1 = 0.f;
            if (bias) { b0 = bias[c]; b1 = bias[c + 1]; }
            float2 v;
            v.x = acc[mt][nt][0] + b0;
            v.y = acc[mt][nt][1] + b1;
            *(float2*)(C + (size_t)r * DIMC + c) = v;
            v.x = acc[mt][nt][2] + b0;
            v.y = acc[mt][nt][3] + b1;
            *(float2*)(C + (size_t)(r + 8) * DIMC + c) = v;
        }
    }
}

__global__ void __launch_bounds__(256)
tgemm_qkv_kernel(const float* __restrict__ X,
                 const float* __restrict__ Wq,
                 const float* __restrict__ Wk,
                 const float* __restrict__ Wv)
{
    const float* W;
    float* C;
    if (blockIdx.z == 0)      { W = Wq; C = g_q; }
    else if (blockIdx.z == 1) { W = Wk; C = g_k; }
    else                      { W = Wv; C = g_v; }
    tgemm_body(X, W, C, nullptr);
}

__global__ void __launch_bounds__(256)
tgemm_proj_kernel(const float* __restrict__ Wp,
                  const float* __restrict__ bp,
                  float* __restrict__ out)
{
    tgemm_body(g_o, Wp, out, bp);
}

// ---------------- grouped attention (unchanged) ----------------
__global__ void __launch_bounds__(128)
attn_kernel(float* __restrict__ O)
{
    const int bx = blockIdx.x;
    const int h  = bx % HEADS;
    const int s  = (bx / HEADS) % GROUPS;
    const int bi = bx / (HEADS * GROUPS);
    const int s1 = s / 7, s2 = s % 7;

    __shared__ float qs[SEQ * 65];
    __shared__ float ks[SEQ * 65];
    __shared__ float vs[SEQ * 65];
    __shared__ float Sm[SEQ * 33];

    const int tid = threadIdx.x;

    for (int idx = tid; idx < SEQ * HEAD_DIM; idx += 128) {
        const int j = idx >> 6, d = idx & 63;
        const int vv = j & 7, t2 = (j >> 3) & 1, t1 = j >> 4;
        const int B = bi * VIEWS + vv;
        const int n = t1 * 98 + s1 * 14 + t2 * 7 + s2;
        const size_t g = ((size_t)(B * NTOK + n)) * DIMC + h * HEAD_DIM + d;
        qs[j * 65 + d] = g_q[g];
        ks[j * 65 + d] = g_k[g];
        vs[j * 65 + d] = g_v[g];
    }
    __syncthreads();

    const int w = tid >> 5, lane = tid & 31;
#pragma unroll 1
    for (int r = 0; r < 8; r++) {
        const int i = w * 8 + r;
        float sum = 0.f;
#pragma unroll
        for (int d = 0; d < HEAD_DIM; d++)
            sum = fmaf(qs[i * 65 + d], ks[lane * 65 + d], sum);
        Sm[i * 33 + lane] = sum * SCALE_ATTN;
    }
    __syncthreads();

    if (tid < SEQ) {
        float m = -1e30f;
#pragma unroll
        for (int j = 0; j < SEQ; j++) m = fmaxf(m, Sm[tid * 33 + j]);
        float sum = 0.f;
#pragma unroll
        for (int j = 0; j < SEQ; j++) {
            const float e = __expf(Sm[tid * 33 + j] - m);
            Sm[tid * 33 + j] = e;
            sum += e;
        }
        const float inv = 1.f / sum;
#pragma unroll
        for (int j = 0; j < SEQ; j++) Sm[tid * 33 + j] *= inv;
    }
    __syncthreads();

    for (int idx = tid; idx < SEQ * HEAD_DIM; idx += 128) {
        const int i = idx >> 6, d = idx & 63;
        float o = 0.f;
#pragma unroll
        for (int j = 0; j < SEQ; j++)
            o = fmaf(Sm[i * 33 + j], vs[j * 65 + d], o);
        const int vv = i & 7, t2 = (i >> 3) & 1, t1 = i >> 4;
        const int B = bi * VIEWS + vv;
        const int n = t1 * 98 + s1 * 14 + t2 * 7 + s2;
        O[((size_t)(B * NTOK + n)) * DIMC + h * HEAD_DIM + d] = o;
    }
}

// ---------------- depthwise 3x3 conv, accumulate into O ----------------
__global__ void __launch_bounds__(256)
conv_kernel(const float* __restrict__ cw,
            const float* __restrict__ cb,
            float* __restrict__ O)
{
    const size_t gid = (size_t)blockIdx.x * 256 + threadIdx.x;
    if (gid >= (size_t)TOTAL_ELEMS) return;
    const int c  = (int)(gid % DIMC);
    const int sp = (int)((gid / DIMC) % NTOK);
    const int B  = (int)(gid / ((size_t)DIMC * NTOK));
    const int x  = sp % GRID_HW, y = sp / GRID_HW;

    float acc = cb[c];
#pragma unroll
    for (int dy = 0; dy < 3; dy++) {
        const int yy = y + dy - 1;
        if (yy < 0 || yy >= GRID_HW) continue;
#pragma unroll
        for (int dx = 0; dx < 3; dx++) {
            const int xx = x + dx - 1;
            if (xx < 0 || xx >= GRID_HW) continue;
            acc = fmaf(g_v[((size_t)(B * NTOK) + yy * GRID_HW + xx) * DIMC + c],
                       cw[c * 9 + dy * 3 + dx], acc);
        }
    }
    O[gid] += acc;
}

// ---------------- launch ----------------
extern "C" void kernel_launch(void* const* d_in, const int* in_sizes, int n_in,
                              void* d_out, int out_size)
{
    const float* x = (const float*)d_in[0];
    int base = (n_in > 1 && in_sizes[1] == 1) ? 2 : 1;
    const float* Wq = (const float*)d_in[base + 0];
    const float* Wk = (const float*)d_in[base + 1];
    const float* Wv = (const float*)d_in[base + 2];
    const float* Wp = (const float*)d_in[base + 3];
    const float* bp = (const float*)d_in[base + 4];
    const float* cw = (const float*)d_in[base + 5];
    const float* cb = (const float*)d_in[base + 6];
    float* out = (float*)d_out;

    float* o_ptr;
    cudaGetSymbolAddress((void**)&o_ptr, g_o);

    dim3 gq(DIMC / 128, M_TOT / 128, 3);
    tgemm_qkv_kernel<<<gq, 256>>>(x, Wq, Wk, Wv);

    attn_kernel<<<BS * GROUPS * HEADS, 128>>>(o_ptr);

    conv_kernel<<<(TOTAL_ELEMS + 255) / 256, 256>>>(cw, cb, o_ptr);

    dim3 gp(DIMC / 128, M_TOT / 128);
    tgemm_proj_kernel<<<gp, 256>>>(Wp, bp, out);
}